// round 2
// baseline (speedup 1.0000x reference)
#include <cuda_runtime.h>

// Problem constants (shapes fixed by the dataset)
#define T_TYPES 8
#define HDIM    128
#define H2DIM   256
#define TILE_M  80          // 150000 % 80 == 0 -> no remainder tiles
#define BK      16
#define NTHREADS 512

// Shared memory layout (floats):
//   Xs: [256][81]  gathered x tile, transposed (k-major), pad 81 vs bank conflicts
//   Hs: [128][81]  hidden tile, transposed
//   Bs: 2 x [16][128]  double-buffered W tile
//   src_s/tgt_s: [80] ints each
#define XS_STRIDE 81
#define XS_FLOATS (H2DIM * XS_STRIDE)          // 20736
#define HS_FLOATS (HDIM * XS_STRIDE)           // 10368
#define BS_FLOATS (BK * HDIM)                  // 2048 per buffer
#define SMEM_FLOATS (XS_FLOATS + HS_FLOATS + 2 * BS_FLOATS)
#define SMEM_BYTES  (SMEM_FLOATS * 4 + 2 * TILE_M * 4)

__global__ void __launch_bounds__(NTHREADS, 1)
relmp_kernel(const float* __restrict__ ns, const int* __restrict__ adj,
             const float* __restrict__ W1, const float* __restrict__ W2,
             float* __restrict__ out, int E)
{
    extern __shared__ float sm[];
    float* Xs  = sm;                        // 256 x 81
    float* Hs  = Xs + XS_FLOATS;            // 128 x 81
    float* Bs0 = Hs + HS_FLOATS;            // 16 x 128
    float* Bs1 = Bs0 + BS_FLOATS;           // 16 x 128
    int*   src_s = (int*)(Bs1 + BS_FLOATS);
    int*   tgt_s = src_s + TILE_M;

    const int t    = blockIdx.y;
    const int e0   = blockIdx.x * TILE_M;
    const int tid  = threadIdx.x;
    const int lane = tid & 31;
    const int wid  = tid >> 5;              // 0..15
    const int tx   = tid & 31;              // 0..31 -> 4 cols each (128 cols)
    const int ty   = tid >> 5;              // 0..15 -> 5 rows each (80 rows)

    // ---- load adjacency for this tile ----
    if (tid < TILE_M) {
        int e = e0 + tid;
        int s, g;
        if (e < E) {
            s = adj[(t * E + e) * 2 + 0];
            g = adj[(t * E + e) * 2 + 1];
        } else { s = 0; g = -1; }
        src_s[tid] = s;
        tgt_s[tid] = g;
    }
    __syncthreads();

    // ---- gather: 160 node rows (80 src then 80 tgt) into transposed Xs ----
    // warp w handles rows w, w+16, ... ; lane loads float4 of the 128-float row
    for (int r = wid; r < 2 * TILE_M; r += 16) {
        int  e    = (r < TILE_M) ? r : (r - TILE_M);
        int  node = (r < TILE_M) ? src_s[e] : tgt_s[e];
        if (node < 0) node = 0;
        int  kbase = (r < TILE_M) ? 0 : HDIM;
        float4 v = *(const float4*)(ns + (size_t)node * HDIM + 4 * lane);
        int k = kbase + 4 * lane;
        Xs[(k + 0) * XS_STRIDE + e] = v.x;
        Xs[(k + 1) * XS_STRIDE + e] = v.y;
        Xs[(k + 2) * XS_STRIDE + e] = v.z;
        Xs[(k + 3) * XS_STRIDE + e] = v.w;
    }

    float acc[5][4];
    #pragma unroll
    for (int i = 0; i < 5; i++)
        #pragma unroll
        for (int j = 0; j < 4; j++) acc[i][j] = 0.f;

    // ---- GEMM1: C[80,128] = X[80,256] * W1[t][256,128], double-buffered Bs ----
    const float* w1t = W1 + (size_t)t * H2DIM * HDIM;
    // preload tile 0 into Bs0
    ((float4*)Bs0)[tid] = ((const float4*)w1t)[tid];
    __syncthreads();   // also orders gather writes to Xs before reads

    #pragma unroll 1
    for (int kt = 0; kt < H2DIM / BK; kt++) {
        float* cur = (kt & 1) ? Bs1 : Bs0;
        float* nxt = (kt & 1) ? Bs0 : Bs1;
        // prefetch next W1 tile into the idle buffer (overlaps with compute)
        if (kt + 1 < H2DIM / BK)
            ((float4*)nxt)[tid] = ((const float4*)(w1t + (kt + 1) * BK * HDIM))[tid];
        const int kb = kt * BK;
        #pragma unroll
        for (int k = 0; k < BK; k++) {
            float a[5];
            const float* xrow = Xs + (kb + k) * XS_STRIDE + 5 * ty;
            #pragma unroll
            for (int i = 0; i < 5; i++) a[i] = xrow[i];          // warp broadcast
            float4 b = *(const float4*)(cur + k * HDIM + 4 * tx); // conflict-free
            #pragma unroll
            for (int i = 0; i < 5; i++) {
                acc[i][0] = fmaf(a[i], b.x, acc[i][0]);
                acc[i][1] = fmaf(a[i], b.y, acc[i][1]);
                acc[i][2] = fmaf(a[i], b.z, acc[i][2]);
                acc[i][3] = fmaf(a[i], b.w, acc[i][3]);
            }
        }
        __syncthreads();   // next buffer staged + all readers done with cur
    }

    // relu -> Hs (transposed, k-major)
    #pragma unroll
    for (int j = 0; j < 4; j++)
        #pragma unroll
        for (int i = 0; i < 5; i++)
            Hs[(4 * tx + j) * XS_STRIDE + 5 * ty + i] = fmaxf(acc[i][j], 0.f);

    #pragma unroll
    for (int i = 0; i < 5; i++)
        #pragma unroll
        for (int j = 0; j < 4; j++) acc[i][j] = 0.f;

    // ---- GEMM2: C[80,128] = H[80,128] * W2[t][128,128], double-buffered ----
    const float* w2t = W2 + (size_t)t * HDIM * HDIM;
    ((float4*)Bs0)[tid] = ((const float4*)w2t)[tid];
    __syncthreads();   // orders Hs writes before reads + Bs0 staged

    #pragma unroll 1
    for (int kt = 0; kt < HDIM / BK; kt++) {
        float* cur = (kt & 1) ? Bs1 : Bs0;
        float* nxt = (kt & 1) ? Bs0 : Bs1;
        if (kt + 1 < HDIM / BK)
            ((float4*)nxt)[tid] = ((const float4*)(w2t + (kt + 1) * BK * HDIM))[tid];
        const int kb = kt * BK;
        #pragma unroll
        for (int k = 0; k < BK; k++) {
            float a[5];
            const float* hrow = Hs + (kb + k) * XS_STRIDE + 5 * ty;
            #pragma unroll
            for (int i = 0; i < 5; i++) a[i] = hrow[i];
            float4 b = *(const float4*)(cur + k * HDIM + 4 * tx);
            #pragma unroll
            for (int i = 0; i < 5; i++) {
                acc[i][0] = fmaf(a[i], b.x, acc[i][0]);
                acc[i][1] = fmaf(a[i], b.y, acc[i][1]);
                acc[i][2] = fmaf(a[i], b.z, acc[i][2]);
                acc[i][3] = fmaf(a[i], b.w, acc[i][3]);
            }
        }
        __syncthreads();
    }

    // ---- epilogue: relu, bounce through smem (reuse Xs), coalesced RED ----
    float* OutS = Xs;   // 80*128 floats, Xs no longer needed
    #pragma unroll
    for (int i = 0; i < 5; i++) {
        float4 v;
        v.x = fmaxf(acc[i][0], 0.f);
        v.y = fmaxf(acc[i][1], 0.f);
        v.z = fmaxf(acc[i][2], 0.f);
        v.w = fmaxf(acc[i][3], 0.f);
        *(float4*)(OutS + (5 * ty + i) * HDIM + 4 * tx) = v;
    }
    __syncthreads();

    // warp w handles rows w, w+16, ... : 128B-coalesced atomic adds
    for (int r = wid; r < TILE_M; r += 16) {
        int tg = tgt_s[r];
        if (tg < 0) continue;
        const float* row = OutS + r * HDIM;
        float* orow = out + (size_t)tg * HDIM;
        #pragma unroll
        for (int c = lane; c < HDIM; c += 32)
            atomicAdd(orow + c, row[c]);
    }
}

__global__ void zero_kernel(float4* __restrict__ p, int n4)
{
    int i = blockIdx.x * blockDim.x + threadIdx.x;
    if (i < n4) p[i] = make_float4(0.f, 0.f, 0.f, 0.f);
}

extern "C" void kernel_launch(void* const* d_in, const int* in_sizes, int n_in,
                              void* d_out, int out_size)
{
    const float* ns  = (const float*)d_in[0];   // [N,128] f32
    const int*   adj = (const int*)d_in[1];     // [T,E,2] i32
    const float* W1  = (const float*)d_in[2];   // [T,256,128] f32
    const float* W2  = (const float*)d_in[3];   // [T,128,128] f32
    float* out = (float*)d_out;                 // [N,128] f32

    int E = in_sizes[1] / (T_TYPES * 2);

    // out is poisoned: zero it first (scatter-add base)
    int n4 = out_size / 4;
    zero_kernel<<<(n4 + 255) / 256, 256>>>((float4*)out, n4);

    cudaFuncSetAttribute(relmp_kernel,
                         cudaFuncAttributeMaxDynamicSharedMemorySize,
                         SMEM_BYTES);
    dim3 grid((E + TILE_M - 1) / TILE_M, T_TYPES);
    relmp_kernel<<<grid, NTHREADS, SMEM_BYTES>>>(ns, adj, W1, W2, out, E);
}

// round 15
// speedup vs baseline: 2.6339x; 2.6339x over previous
#include <cuda_runtime.h>
#include <cstdint>

// ---------------- problem constants ----------------
#define T_TYPES 8
#define HDIM    128
#define H2DIM   256
#define TILE_M  128
#define NTHREADS 256

// smem strides (floats):
//  A-operand strides ≡ 4 (mod 32): A-fragment banks = 4g+t -> conflict-free
//  B-operand stride  ≡ 8 (mod 32): B-fragment banks = 8t+g -> conflict-free
#define XS_STRIDE 260     // X tile   [128][260], stride%32 = 4
#define HS_STRIDE 132     // H / Out  [128][132], stride%32 = 4
#define WS_STRIDE 136     // W chunks [64][136],  stride%32 = 8

// smem layout (bytes)
#define SM_SRC   0
#define SM_TGT   512
#define SM_XS    1024
#define XS_BYTES (TILE_M * XS_STRIDE * 4)          // 133120
#define SM_B0    (SM_XS + XS_BYTES)                // 134144
#define WB_BYTES (64 * WS_STRIDE * 4)              // 34816
#define SM_B1    (SM_B0 + WB_BYTES)                // 168960
#define SMEM_TOTAL (SM_B1 + WB_BYTES)              // 203776

__device__ __forceinline__ float tf32r(float x) {
    float r; asm("cvt.rna.tf32.f32 %0, %1;" : "=f"(r) : "f"(x)); return r;
}

// m16n8k8 tf32 mma (sm_80+ feature set -> compiles for plain sm_103 target)
__device__ __forceinline__ void mma_tf32(float* c, const uint32_t* a, const uint32_t* b) {
    asm volatile(
        "mma.sync.aligned.m16n8k8.row.col.f32.tf32.tf32.f32 "
        "{%0,%1,%2,%3}, {%4,%5,%6,%7}, {%8,%9}, {%0,%1,%2,%3};"
        : "+f"(c[0]), "+f"(c[1]), "+f"(c[2]), "+f"(c[3])
        : "r"(a[0]), "r"(a[1]), "r"(a[2]), "r"(a[3]), "r"(b[0]), "r"(b[1]));
}

__global__ void zero_kernel(float4* __restrict__ p, int n4) {
    int i = blockIdx.x * blockDim.x + threadIdx.x;
    if (i < n4) p[i] = make_float4(0.f, 0.f, 0.f, 0.f);
}

// stage one [64k][128n] weight chunk (row-major [k][n]) into smem, tf32-rounded
__device__ __forceinline__ void stage_w(const float* __restrict__ src, int k0,
                                        float* buf, int tid) {
    #pragma unroll
    for (int i = 0; i < 8; i++) {
        int f = tid + i * NTHREADS;          // 2048 float4s
        int row = f >> 5;                    // 0..63
        int c = (f & 31) << 2;               // 0..124
        float4 v = *(const float4*)(src + (size_t)(k0 + row) * HDIM + c);
        v.x = tf32r(v.x); v.y = tf32r(v.y); v.z = tf32r(v.z); v.w = tf32r(v.w);
        *(float4*)(buf + row * WS_STRIDE + c) = v;
    }
}

// one 64-k chunk: A [128][astride] rows m0w.., k kbase..kbase+63 ; W chunk [64][WS_STRIDE]
__device__ __forceinline__ void gemm_chunk(const float* __restrict__ A, int astride,
                                           int kbase, const float* __restrict__ Wc,
                                           int m0w, int n0w, int g, int t,
                                           float acc[4][4][4]) {
    #pragma unroll 1
    for (int kt = 0; kt < 8; kt++) {
        uint32_t a[4][4], b[4][2];
        const int k0 = kbase + kt * 8;
        #pragma unroll
        for (int mi = 0; mi < 4; mi++) {
            const float* ap = A + (size_t)(m0w + mi * 16 + g) * astride + k0 + t;
            a[mi][0] = __float_as_uint(ap[0]);                          // A[g   ][t  ]
            a[mi][1] = __float_as_uint(ap[8 * (size_t)astride]);        // A[g+8 ][t  ]
            a[mi][2] = __float_as_uint(ap[4]);                          // A[g   ][t+4]
            a[mi][3] = __float_as_uint(ap[8 * (size_t)astride + 4]);    // A[g+8 ][t+4]
        }
        #pragma unroll
        for (int ni = 0; ni < 4; ni++) {
            const float* bp = Wc + (size_t)(kt * 8 + t) * WS_STRIDE + n0w + ni * 8 + g;
            b[ni][0] = __float_as_uint(bp[0]);                          // B[t  ][g]
            b[ni][1] = __float_as_uint(bp[4 * WS_STRIDE]);              // B[t+4][g]
        }
        #pragma unroll
        for (int mi = 0; mi < 4; mi++)
            #pragma unroll
            for (int ni = 0; ni < 4; ni++)
                mma_tf32(acc[mi][ni], a[mi], b[ni]);
    }
}

__global__ void __launch_bounds__(NTHREADS, 1)
relmp_mma(const float* __restrict__ ns, const int* __restrict__ adj,
          const float* __restrict__ W1, const float* __restrict__ W2,
          float* __restrict__ out, int E)
{
    extern __shared__ float sm[];
    int*   src_s = (int*)((char*)sm + SM_SRC);
    int*   tgt_s = (int*)((char*)sm + SM_TGT);
    float* Xs    = (float*)((char*)sm + SM_XS);      // [128][260]
    float* Hs    = Xs;                                // [128][132] overlay (post-GEMM1)
    float* Bb[2] = { (float*)((char*)sm + SM_B0), (float*)((char*)sm + SM_B1) };

    const int tid  = threadIdx.x;
    const int wid  = tid >> 5;
    const int lane = tid & 31;
    const int g    = lane >> 2;            // fragment group 0..7
    const int t    = lane & 3;             // thread-in-group 0..3
    const int m0w  = (wid & 1) * 64;       // warp M origin (2 warps over M)
    const int n0w  = (wid >> 1) * 32;      // warp N origin (4 warps over N)
    const int ty   = blockIdx.y;
    const int e0   = blockIdx.x * TILE_M;

    // adjacency
    if (tid < TILE_M) {
        int e = e0 + tid;
        int s = 0, gg = -1;
        if (e < E) {
            s  = adj[((size_t)ty * E + e) * 2 + 0];
            gg = adj[((size_t)ty * E + e) * 2 + 1];
        }
        src_s[tid] = s;
        tgt_s[tid] = gg;
    }
    __syncthreads();

    const float* w1t = W1 + (size_t)ty * H2DIM * HDIM;   // [256][128] row-major = B-ready
    const float* w2t = W2 + (size_t)ty * HDIM * HDIM;    // [128][128]

    // stage W1 chunk0 while gathering
    stage_w(w1t, 0, Bb[0], tid);

    // gather 256 node rows (128 src then 128 tgt) into Xs, tf32-rounded
    #pragma unroll 4
    for (int it = 0; it < 32; it++) {
        int r = it * 8 + wid;
        int e = r & (TILE_M - 1);
        int kb = (r < TILE_M) ? 0 : HDIM;
        int node = (r < TILE_M) ? src_s[e] : tgt_s[e];
        if (node < 0) node = 0;
        float4 v = *(const float4*)(ns + (size_t)node * HDIM + 4 * lane);
        v.x = tf32r(v.x); v.y = tf32r(v.y); v.z = tf32r(v.z); v.w = tf32r(v.w);
        *(float4*)(Xs + (size_t)e * XS_STRIDE + kb + 4 * lane) = v;
    }
    __syncthreads();

    float acc[4][4][4];
    #pragma unroll
    for (int mi = 0; mi < 4; mi++)
        #pragma unroll
        for (int ni = 0; ni < 4; ni++)
            #pragma unroll
            for (int j = 0; j < 4; j++) acc[mi][ni][j] = 0.f;

    // ---- GEMM1: C[128,128] = X[128,256] @ W1, 4 k-chunks of 64, double-buffered W ----
    #pragma unroll 1
    for (int c = 0; c < 4; c++) {
        if (c < 3)      stage_w(w1t, (c + 1) * 64, Bb[(c + 1) & 1], tid);
        else            stage_w(w2t, 0, Bb[0], tid);   // prefetch W2 chunk0 -> buf0
        gemm_chunk(Xs, XS_STRIDE, c * 64, Bb[c & 1], m0w, n0w, g, t, acc);
        __syncthreads();   // staged buffer visible + all reads of current done
    }

    // ---- epilogue 1: relu -> tf32 -> Hs (overlay Xs; all GEMM1 reads done) ----
    #pragma unroll
    for (int mi = 0; mi < 4; mi++)
        #pragma unroll
        for (int ni = 0; ni < 4; ni++) {
            int r0 = m0w + mi * 16 + g;
            int n  = n0w + ni * 8 + 2 * t;
            float2 v0, v1;
            v0.x = tf32r(fmaxf(acc[mi][ni][0], 0.f));
            v0.y = tf32r(fmaxf(acc[mi][ni][1], 0.f));
            v1.x = tf32r(fmaxf(acc[mi][ni][2], 0.f));
            v1.y = tf32r(fmaxf(acc[mi][ni][3], 0.f));
            *(float2*)(Hs + (size_t)r0 * HS_STRIDE + n) = v0;
            *(float2*)(Hs + (size_t)(r0 + 8) * HS_STRIDE + n) = v1;
            acc[mi][ni][0] = 0.f; acc[mi][ni][1] = 0.f;
            acc[mi][ni][2] = 0.f; acc[mi][ni][3] = 0.f;
        }
    __syncthreads();

    // ---- GEMM2: C = H[128,128] @ W2, 2 k-chunks of 64 (buf0 pre-staged) ----
    #pragma unroll 1
    for (int c = 0; c < 2; c++) {
        if (c == 0) stage_w(w2t, 64, Bb[1], tid);
        gemm_chunk(Hs, HS_STRIDE, c * 64, Bb[c & 1], m0w, n0w, g, t, acc);
        __syncthreads();
    }

    // ---- epilogue 2: relu -> OutS (reuse Hs region; GEMM2 reads done) ----
    float* OutS = Hs;
    #pragma unroll
    for (int mi = 0; mi < 4; mi++)
        #pragma unroll
        for (int ni = 0; ni < 4; ni++) {
            int r0 = m0w + mi * 16 + g;
            int n  = n0w + ni * 8 + 2 * t;
            float2 v0, v1;
            v0.x = fmaxf(acc[mi][ni][0], 0.f);
            v0.y = fmaxf(acc[mi][ni][1], 0.f);
            v1.x = fmaxf(acc[mi][ni][2], 0.f);
            v1.y = fmaxf(acc[mi][ni][3], 0.f);
            *(float2*)(OutS + (size_t)r0 * HS_STRIDE + n) = v0;
            *(float2*)(OutS + (size_t)(r0 + 8) * HS_STRIDE + n) = v1;
        }
    __syncthreads();

    // ---- scatter: coalesced atomicAdd per edge row ----
    for (int rr = wid; rr < TILE_M; rr += 8) {
        int tg = tgt_s[rr];
        if (tg < 0) continue;
        float* orow = out + (size_t)tg * HDIM;
        #pragma unroll
        for (int itc = 0; itc < 4; itc++) {
            int cc = itc * 32 + lane;
            atomicAdd(orow + cc, OutS[(size_t)rr * HS_STRIDE + cc]);
        }
    }
}

extern "C" void kernel_launch(void* const* d_in, const int* in_sizes, int n_in,
                              void* d_out, int out_size)
{
    const float* ns  = (const float*)d_in[0];   // [N,128] f32
    const int*   adj = (const int*)d_in[1];     // [T,E,2] i32
    const float* W1  = (const float*)d_in[2];   // [T,256,128] f32
    const float* W2  = (const float*)d_in[3];   // [T,128,128] f32
    float* out = (float*)d_out;                 // [N,128] f32

    int E = in_sizes[1] / (T_TYPES * 2);

    int n4 = out_size / 4;
    zero_kernel<<<(n4 + 255) / 256, 256>>>((float4*)out, n4);

    cudaFuncSetAttribute(relmp_mma, cudaFuncAttributeMaxDynamicSharedMemorySize,
                         SMEM_TOTAL);
    dim3 grid((E + TILE_M - 1) / TILE_M, T_TYPES);
    relmp_mma<<<grid, NTHREADS, SMEM_TOTAL>>>(ns, adj, W1, W2, out, E);
}